// round 1
// baseline (speedup 1.0000x reference)
#include <cuda_runtime.h>

// EMA scan: h_t = a*x_t + (1-a)*h_{t-1} along T (innermost axis).
// Exploits geometric decay: (1-a)^32 = 0.6^32 ~ 8e-8, so each chunk of C
// elements can be computed independently using a W-element warmup window.
//
// Layout: inp [B, D, T] fp32, T=innermost (stride 1). rows = B*D independent
// sequences. Each thread owns one chunk of C=128 contiguous elements.

#define CHUNK 128
#define WARMUP 32
#define EMA_A 0.4f
#define EMA_OMA 0.6f

__global__ void __launch_bounds__(256) ema_kernel(
    const float* __restrict__ x,
    const float* __restrict__ h0,
    float* __restrict__ y,
    int T, int chunks_per_row, int total)
{
    int tid = blockIdx.x * blockDim.x + threadIdx.x;
    if (tid >= total) return;

    int row = tid / chunks_per_row;
    int c   = tid % chunks_per_row;

    size_t base = (size_t)row * (size_t)T + (size_t)c * CHUNK;
    const float* xp = x + base;

    float h;
    if (c == 0) {
        h = h0[row];
    } else {
        // Warmup: start from 0, run WARMUP steps before the chunk.
        // Truncation error <= 0.6^WARMUP * |h_true| ~ 8e-8 — below tolerance.
        h = 0.0f;
        const float4* wv = reinterpret_cast<const float4*>(xp - WARMUP);
        #pragma unroll
        for (int i = 0; i < WARMUP / 4; i++) {
            float4 v = wv[i];
            h = fmaf(EMA_A, v.x, EMA_OMA * h);
            h = fmaf(EMA_A, v.y, EMA_OMA * h);
            h = fmaf(EMA_A, v.z, EMA_OMA * h);
            h = fmaf(EMA_A, v.w, EMA_OMA * h);
        }
    }

    const float4* xv = reinterpret_cast<const float4*>(xp);
    float4* yv = reinterpret_cast<float4*>(y + base);
    #pragma unroll
    for (int i = 0; i < CHUNK / 4; i++) {
        float4 v = xv[i];
        float4 o;
        h = fmaf(EMA_A, v.x, EMA_OMA * h); o.x = h;
        h = fmaf(EMA_A, v.y, EMA_OMA * h); o.y = h;
        h = fmaf(EMA_A, v.z, EMA_OMA * h); o.z = h;
        h = fmaf(EMA_A, v.w, EMA_OMA * h); o.w = h;
        yv[i] = o;
    }
}

extern "C" void kernel_launch(void* const* d_in, const int* in_sizes, int n_in,
                              void* d_out, int out_size)
{
    const float* x  = (const float*)d_in[0];   // inp   [B, D, T]
    const float* h0 = (const float*)d_in[1];   // hidden [B, D, 1]
    float* y = (float*)d_out;

    int rows = in_sizes[1];               // B*D = 8192
    int T = in_sizes[0] / rows;           // 4096
    int chunks_per_row = T / CHUNK;       // 32
    int total = rows * chunks_per_row;    // 262144

    int threads = 256;
    int blocks = (total + threads - 1) / threads;
    ema_kernel<<<blocks, threads>>>(x, h0, y, T, chunks_per_row, total);
}

// round 2
// speedup vs baseline: 1.0170x; 1.0170x over previous
#include <cuda_runtime.h>

// EMA scan: h_t = a*x_t + (1-a)*h_{t-1} along T (innermost).
// Chunked-parallel via geometric decay (0.6^32 ~ 8e-8 << 1e-3 tolerance).
//
// R2 change: prefix recombination. For a group of 4 elements compute
// h-independent prefixes p_j = sum_{i<=j} oma^{j-i} * a * x_i, then
// o_j = oma^j * h + p_j, carry h = o_4. Critical h-chain: 1 FMA per 4
// elements (was 2 dependent ops per element). Prefix chains + loads
// pipeline across groups -> high MLP, latency hidden.

#define CHUNK 128
#define WARMUP 32
#define A    0.4f
#define OMA  0.6f
#define OMA2 0.36f
#define OMA3 0.216f
#define OMA4 0.1296f

__global__ void __launch_bounds__(256) ema_kernel(
    const float* __restrict__ x,
    const float* __restrict__ h0,
    float* __restrict__ y,
    int T, int chunks_per_row, int total)
{
    int tid = blockIdx.x * blockDim.x + threadIdx.x;
    if (tid >= total) return;

    int row = tid / chunks_per_row;
    int c   = tid % chunks_per_row;

    size_t base = (size_t)row * (size_t)T + (size_t)c * CHUNK;
    const float* xp = x + base;

    float h;
    if (c == 0) {
        h = h0[row];
    } else {
        // Warmup from zero state: truncation <= 0.6^32 * |h| ~ 8e-8.
        // One FMA on the h-chain per 4 elements.
        h = 0.0f;
        const float4* wv = reinterpret_cast<const float4*>(xp - WARMUP);
        #pragma unroll
        for (int i = 0; i < WARMUP / 4; i++) {
            float4 v = wv[i];
            float p1 = A * v.x;
            float p2 = fmaf(A, v.y, OMA * p1);
            float p3 = fmaf(A, v.z, OMA * p2);
            float p4 = fmaf(A, v.w, OMA * p3);
            h = fmaf(OMA4, h, p4);
        }
    }

    const float4* xv = reinterpret_cast<const float4*>(xp);
    float4* yv = reinterpret_cast<float4*>(y + base);
    #pragma unroll
    for (int i = 0; i < CHUNK / 4; i++) {
        float4 v = xv[i];
        // h-independent prefixes (pipeline across iterations)
        float p1 = A * v.x;
        float p2 = fmaf(A, v.y, OMA * p1);
        float p3 = fmaf(A, v.z, OMA * p2);
        float p4 = fmaf(A, v.w, OMA * p3);
        // fan-out from h: all 4 outputs independent given h
        float4 o;
        o.x = fmaf(OMA,  h, p1);
        o.y = fmaf(OMA2, h, p2);
        o.z = fmaf(OMA3, h, p3);
        o.w = fmaf(OMA4, h, p4);   // == next h; single FMA on critical path
        h = o.w;
        yv[i] = o;
    }
}

extern "C" void kernel_launch(void* const* d_in, const int* in_sizes, int n_in,
                              void* d_out, int out_size)
{
    const float* x  = (const float*)d_in[0];   // inp    [B, D, T]
    const float* h0 = (const float*)d_in[1];   // hidden [B, D, 1]
    float* y = (float*)d_out;

    int rows = in_sizes[1];               // B*D = 8192
    int T = in_sizes[0] / rows;           // 4096
    int chunks_per_row = T / CHUNK;       // 32
    int total = rows * chunks_per_row;    // 262144

    int threads = 256;
    int blocks = (total + threads - 1) / threads;
    ema_kernel<<<blocks, threads>>>(x, h0, y, T, chunks_per_row, total);
}

// round 3
// speedup vs baseline: 2.1463x; 2.1104x over previous
#include <cuda_runtime.h>

// EMA scan h_t = a*x_t + (1-a)*h_{t-1}, T innermost. R3: warp-cooperative,
// fully coalesced. One warp per row (T=4096 = 32 tiles of 128 elements).
//
// Per tile: lane L loads float4 = elements 4L..4L+3 (coalesced LDG.128).
//   s_j = lane-local weighted prefix of its 4 elements
//   I(L) = Kogge-Stone shuffle scan of s_3 with uniform decay d=0.6^4
//   h_{4L+j} = s_j + 0.6^{j+1} * ( I(L-1) + 0.6^{4L} * h_in )
//   carry: h_in' = I(31) + 0.6^128 * h_in   (exact — no warmup approximation)

#define A    0.4f
#define OMA  0.6f
#define OMA2 0.36f
#define OMA3 0.216f
#define OMA4 0.1296f
#define TILE 128
#define FULL 0xFFFFFFFFu

__global__ void __launch_bounds__(256) ema_warp_kernel(
    const float* __restrict__ x,
    const float* __restrict__ h0,
    float* __restrict__ y,
    int T, int rows)
{
    int gwarp = (blockIdx.x * blockDim.x + threadIdx.x) >> 5;  // one warp = one row
    int lane  = threadIdx.x & 31;
    if (gwarp >= rows) return;

    const float4* xr = reinterpret_cast<const float4*>(x + (size_t)gwarp * T);
    float4*       yr = reinterpret_cast<float4*>(y + (size_t)gwarp * T);

    float h = h0[gwarp];

    // per-lane constant 0.6^(4*lane); decays to ~3e-28 at lane 31 (still normal fp32)
    float d4L = __powf(OMA4, (float)lane);
    const float d128 = 2.4633073e-29f;  // 0.6^128

    int ntiles = T / TILE;
    for (int t = 0; t < ntiles; t++) {
        float4 v = xr[t * 32 + lane];

        // lane-local weighted prefixes (h-independent)
        float s0 = A * v.x;
        float s1 = fmaf(A, v.y, OMA  * s0);
        float s2 = fmaf(A, v.z, OMA  * s1);
        float s3 = fmaf(A, v.w, OMA  * s2);

        // Kogge-Stone inclusive scan of s3 across lanes, decay 0.6^4 per lane
        float I = s3;
        float w = OMA4;
        #pragma unroll
        for (int off = 1; off < 32; off <<= 1) {
            float u = __shfl_up_sync(FULL, I, off);
            if (lane >= off) I = fmaf(w, u, I);
            w = w * w;
        }

        // exclusive-scan value for this lane
        float Bv = __shfl_up_sync(FULL, I, 1);
        if (lane == 0) Bv = 0.0f;

        // fold in the incoming state
        float C = fmaf(d4L, h, Bv);

        float4 o;
        o.x = fmaf(OMA,  C, s0);
        o.y = fmaf(OMA2, C, s1);
        o.z = fmaf(OMA3, C, s2);
        o.w = fmaf(OMA4, C, s3);
        yr[t * 32 + lane] = o;

        // carry: exact next state (I(31) independent of h -> no serial chain)
        float I31 = __shfl_sync(FULL, I, 31);
        h = fmaf(d128, h, I31);
    }
}

extern "C" void kernel_launch(void* const* d_in, const int* in_sizes, int n_in,
                              void* d_out, int out_size)
{
    const float* x  = (const float*)d_in[0];   // inp    [B, D, T]
    const float* h0 = (const float*)d_in[1];   // hidden [B, D, 1]
    float* y = (float*)d_out;

    int rows = in_sizes[1];        // B*D = 8192
    int T = in_sizes[0] / rows;    // 4096

    int threads = 256;                       // 8 warps/block -> 8 rows/block
    int blocks = (rows * 32 + threads - 1) / threads;
    ema_warp_kernel<<<blocks, threads>>>(x, h0, y, T, rows);
}